// round 3
// baseline (speedup 1.0000x reference)
#include <cuda_runtime.h>
#include <cstdint>

#define ULL unsigned long long

__device__ __forceinline__ ULL pk2(float lo, float hi) {
    ULL r; asm("mov.b64 %0, {%1,%2};" : "=l"(r) : "f"(lo), "f"(hi)); return r;
}
__device__ __forceinline__ void upk2(ULL v, float& lo, float& hi) {
    asm("mov.b64 {%0,%1}, %2;" : "=f"(lo), "=f"(hi) : "l"(v));
}
__device__ __forceinline__ ULL fma2(ULL a, ULL b, ULL c) {
    ULL d; asm("fma.rn.f32x2 %0, %1, %2, %3;" : "=l"(d) : "l"(a), "l"(b), "l"(c)); return d;
}
__device__ __forceinline__ ULL mul2(ULL a, ULL b) {
    ULL d; asm("mul.rn.f32x2 %0, %1, %2;" : "=l"(d) : "l"(a), "l"(b)); return d;
}
__device__ __forceinline__ ULL add2(ULL a, ULL b) {
    ULL d; asm("add.rn.f32x2 %0, %1, %2;" : "=l"(d) : "l"(a), "l"(b)); return d;
}
__device__ __forceinline__ ULL relu2(ULL v) {
    float lo, hi; upk2(v, lo, hi);
    lo = fmaxf(lo, 0.0f); hi = fmaxf(hi, 0.0f);
    return pk2(lo, hi);
}
__device__ __forceinline__ ULL splat2(float v) { return pk2(v, v); }

// ---------------------------------------------------------------------------
// Precomputed weights (device globals, no allocation)
// g_WcP: paired layout [98][64]: entry k*64 + ty*4 + c  holds weight for
//        output j = (c<2 ? 2ty+c : 32 + 2ty + (c-2)), input k of combined X.
// ---------------------------------------------------------------------------
__device__ float g_WcP[98 * 64];
__device__ float g_W0t[64 * 32];   // [k][j]
__device__ float g_W1t[32 * 32];   // [k][j]

__global__ void nnue_setup_kernel(const float* __restrict__ Ww,
                                  const float* __restrict__ Wb,
                                  const float* __restrict__ W0,
                                  const float* __restrict__ W1) {
    int t = blockIdx.x * blockDim.x + threadIdx.x;
    if (t < 98 * 64) {
        int k = t >> 6, q = t & 63;
        int ty = q >> 2, c = q & 3;
        int j = (c < 2) ? (2 * ty + c) : (32 + 2 * ty + (c - 2));
        float v;
        if (j < 32) {
            v = Ww[j * 98 + k];
        } else {
            int kk = k + 49; if (kk >= 98) kk -= 98;
            v = Wb[(j - 32) * 98 + kk];
        }
        g_WcP[t] = v;
    }
    if (t < 64 * 32) { int k = t >> 5, j = t & 31; g_W0t[t] = W0[j * 64 + k]; }
    if (t < 32 * 32) { int k = t >> 5, j = t & 31; g_W1t[t] = W1[j * 32 + k]; }
}

// ---------------------------------------------------------------------------
// Shared layout (float offsets). XSTR = 130 (stride ≡ 2 mod 32 -> 2-way max).
// Region A (XS) reused as `base`; region B (WcP copy) reused as x0 + partials.
// ---------------------------------------------------------------------------
constexpr int XSTR     = 130;
constexpr int OFF_XS   = 0;                   // [98][130]
constexpr int OFF_BASE = 0;                   // [64][130]  (aliases XS)
constexpr int OFF_WC   = 98 * XSTR;           // [98][64]   = 12740
constexpr int OFF_X0   = OFF_WC;              // [32][130]  (aliases WC)
constexpr int OFF_PART = OFF_WC + 32 * XSTR;  // [16][130]
constexpr int OFF_W0T  = OFF_WC + 98 * 64;    // 19012
constexpr int OFF_W1T  = OFF_W0T + 64 * 32;   // 21060
constexpr int OFF_B1P  = OFF_W1T + 32 * 32;   // 22084 [16]x float4
constexpr int OFF_W2   = OFF_B1P + 64;        // 22148 [64]
constexpr int OFF_B0   = OFF_W2 + 64;         // [32]
constexpr int OFF_B1V  = OFF_B0 + 32;         // [32]
constexpr int OFF_B2   = OFF_B1V + 32;        // [1]
constexpr int OFF_POV  = OFF_B2 + 2;          // [128], even offset (8B aligned)
constexpr int SMEM_FLOATS = OFF_POV + 128;
constexpr int SMEM_BYTES  = SMEM_FLOATS * 4;  // ~89.6 KB -> 2 blocks/SM

__global__ __launch_bounds__(256, 2)
void nnue_kernel(const float* __restrict__ pov,
                 const float* __restrict__ white,
                 const float* __restrict__ black,
                 const float* __restrict__ bwp,
                 const float* __restrict__ bbp,
                 const float* __restrict__ b0p,
                 const float* __restrict__ b1p,
                 const float* __restrict__ W2p,
                 const float* __restrict__ b2p,
                 float* __restrict__ out) {
    extern __shared__ float sh[];
    const int t  = threadIdx.x;
    const int s0 = blockIdx.x * 128;

    // ---- load phase -------------------------------------------------------
    // inputs: float4 coalesced reads, transpose-scatter stores (2-way max)
    {
        const float4* w4p = (const float4*)(white + s0 * 49);
        const float4* b4p = (const float4*)(black + s0 * 49);
        for (int i4 = t; i4 < 1568; i4 += 256) {
            float4 wv = w4p[i4];
            float4 bv = b4p[i4];
            float wf[4] = {wv.x, wv.y, wv.z, wv.w};
            float bf[4] = {bv.x, bv.y, bv.z, bv.w};
            int ibase = i4 * 4;
#pragma unroll
            for (int c = 0; c < 4; c++) {
                int i = ibase + c;
                int s = (unsigned)i / 49u;
                int k = i - s * 49;
                sh[OFF_XS + k * XSTR + s]        = wf[c];
                sh[OFF_XS + (49 + k) * XSTR + s] = bf[c];
            }
        }
    }
    for (int i = t; i < 98 * 64; i += 256) sh[OFF_WC  + i] = g_WcP[i];
    for (int i = t; i < 64 * 32; i += 256) sh[OFF_W0T + i] = g_W0t[i];
    for (int i = t; i < 32 * 32; i += 256) sh[OFF_W1T + i] = g_W1t[i];
    if (t < 16) {
        // paired stage-1 bias: {bw[2t], bw[2t+1], bb[2t], bb[2t+1]}
        sh[OFF_B1P + t * 4 + 0] = bwp[2 * t];
        sh[OFF_B1P + t * 4 + 1] = bwp[2 * t + 1];
        sh[OFF_B1P + t * 4 + 2] = bbp[2 * t];
        sh[OFF_B1P + t * 4 + 3] = bbp[2 * t + 1];
    }
    if (t < 64)  sh[OFF_W2  + t] = W2p[t];
    if (t < 32)  sh[OFF_B0  + t] = b0p[t];
    if (t < 32)  sh[OFF_B1V + t] = b1p[t];
    if (t == 0)  sh[OFF_B2]      = b2p[0];
    if (t < 128) sh[OFF_POV + t] = pov[s0 + t];
    __syncthreads();

    // ---- stage 1: 128 samples x 64 outputs, K=98 --------------------------
    // thread: samples s = tx*2 + g*32 (4 f32x2 pairs), outputs {2ty,2ty+1,+32,+33}
    const int tx = t & 15;
    const int ty = t >> 4;

    ULL acc[4][4];
#pragma unroll
    for (int c = 0; c < 4; c++)
#pragma unroll
        for (int g = 0; g < 4; g++) acc[c][g] = 0ull;

    {
        const float* xb = sh + OFF_XS + tx * 2;
        const float* wb = sh + OFF_WC + ty * 4;

        ULL   xc[4];
        float4 wc;
#pragma unroll
        for (int g = 0; g < 4; g++) xc[g] = *(const ULL*)(xb + g * 32);
        wc = *(const float4*)(wb);

#pragma unroll 2
        for (int k = 0; k < 98; k++) {
            // prefetch k+1 (row 98 reads spill into WcP region: in-bounds, unused)
            ULL xn[4];
            const float* xr = xb + (k + 1) * XSTR;
#pragma unroll
            for (int g = 0; g < 4; g++) xn[g] = *(const ULL*)(xr + g * 32);
            float4 wn = *(const float4*)(wb + (k + 1) * 64);

            float wf[4] = {wc.x, wc.y, wc.z, wc.w};
#pragma unroll
            for (int c = 0; c < 4; c++) {
                ULL ws = splat2(wf[c]);
#pragma unroll
                for (int g = 0; g < 4; g++)
                    acc[c][g] = fma2(ws, xc[g], acc[c][g]);
            }
#pragma unroll
            for (int g = 0; g < 4; g++) xc[g] = xn[g];
            wc = wn;
        }
    }

    // ---- bias + perspective mix + relu, all in registers ------------------
    {
        float4 bp = *(const float4*)(sh + OFF_B1P + ty * 4);
        float bL[2] = {bp.x, bp.y};
        float bH[2] = {bp.z, bp.w};
#pragma unroll
        for (int g = 0; g < 4; g++) {
            ULL pp = *(const ULL*)(sh + OFF_POV + tx * 2 + g * 32);
            float p0, p1; upk2(pp, p0, p1);
            ULL op = pk2(1.0f - p0, 1.0f - p1);
#pragma unroll
            for (int d = 0; d < 2; d++) {
                ULL sL = add2(acc[d][g],     splat2(bL[d]));
                ULL sH = add2(acc[d + 2][g], splat2(bH[d]));
                ULL v0 = fma2(pp, sL, mul2(op, sH));   // base[j]
                ULL v1 = fma2(pp, sH, mul2(op, sL));   // base[j+32]
                acc[d][g]     = relu2(v0);
                acc[d + 2][g] = relu2(v1);
            }
        }
    }
    __syncthreads();   // all reads of XS done before overwriting with base

    {
#pragma unroll
        for (int g = 0; g < 4; g++) {
            int s = tx * 2 + g * 32;
#pragma unroll
            for (int d = 0; d < 2; d++) {
                *(ULL*)(sh + OFF_BASE + (2 * ty + d)      * XSTR + s) = acc[d][g];
                *(ULL*)(sh + OFF_BASE + (2 * ty + d + 32) * XSTR + s) = acc[d + 2][g];
            }
        }
    }
    __syncthreads();

    // ---- stage 2a: x0 = relu(base @ W0t + b0), + partial W2 dot -----------
    // thread: samples s = tx2*2 + sp*64 (2 pairs), outputs ty2*4..+3
    const int tx2 = t & 31;
    const int ty2 = t >> 5;

    ULL a0[4][2];
#pragma unroll
    for (int c = 0; c < 4; c++) { a0[c][0] = 0ull; a0[c][1] = 0ull; }
    {
        const float* xb = sh + OFF_BASE + tx2 * 2;
        const float* wb = sh + OFF_W0T + ty2 * 4;
#pragma unroll 4
        for (int k = 0; k < 64; k++) {
            ULL x0v = *(const ULL*)(xb + k * XSTR);
            ULL x1v = *(const ULL*)(xb + k * XSTR + 64);
            float4 w4 = *(const float4*)(wb + k * 32);
            float wf[4] = {w4.x, w4.y, w4.z, w4.w};
#pragma unroll
            for (int c = 0; c < 4; c++) {
                ULL ws = splat2(wf[c]);
                a0[c][0] = fma2(ws, x0v, a0[c][0]);
                a0[c][1] = fma2(ws, x1v, a0[c][1]);
            }
        }
    }
    {
        ULL pac[2] = {0ull, 0ull};
#pragma unroll
        for (int c = 0; c < 4; c++) {
            int j = ty2 * 4 + c;
            ULL bs  = splat2(sh[OFF_B0 + j]);
            ULL w2s = splat2(sh[OFF_W2 + j]);
#pragma unroll
            for (int sp = 0; sp < 2; sp++) {
                ULL v = relu2(add2(a0[c][sp], bs));
                *(ULL*)(sh + OFF_X0 + j * XSTR + tx2 * 2 + sp * 64) = v;
                pac[sp] = fma2(w2s, v, pac[sp]);
            }
        }
#pragma unroll
        for (int sp = 0; sp < 2; sp++)
            *(ULL*)(sh + OFF_PART + ty2 * XSTR + tx2 * 2 + sp * 64) = pac[sp];
    }
    __syncthreads();

    // ---- stage 2b: x1 = relu(x0 @ W1t + b1), + partial W2[32:] dot --------
    ULL a1[4][2];
#pragma unroll
    for (int c = 0; c < 4; c++) { a1[c][0] = 0ull; a1[c][1] = 0ull; }
    {
        const float* xb = sh + OFF_X0 + tx2 * 2;
        const float* wb = sh + OFF_W1T + ty2 * 4;
#pragma unroll 4
        for (int k = 0; k < 32; k++) {
            ULL x0v = *(const ULL*)(xb + k * XSTR);
            ULL x1v = *(const ULL*)(xb + k * XSTR + 64);
            float4 w4 = *(const float4*)(wb + k * 32);
            float wf[4] = {w4.x, w4.y, w4.z, w4.w};
#pragma unroll
            for (int c = 0; c < 4; c++) {
                ULL ws = splat2(wf[c]);
                a1[c][0] = fma2(ws, x0v, a1[c][0]);
                a1[c][1] = fma2(ws, x1v, a1[c][1]);
            }
        }
    }
    {
        ULL pac[2] = {0ull, 0ull};
#pragma unroll
        for (int c = 0; c < 4; c++) {
            int j = ty2 * 4 + c;
            ULL bs  = splat2(sh[OFF_B1V + j]);
            ULL w2s = splat2(sh[OFF_W2 + 32 + j]);
#pragma unroll
            for (int sp = 0; sp < 2; sp++) {
                ULL v = relu2(add2(a1[c][sp], bs));
                pac[sp] = fma2(w2s, v, pac[sp]);
            }
        }
#pragma unroll
        for (int sp = 0; sp < 2; sp++)
            *(ULL*)(sh + OFF_PART + (8 + ty2) * XSTR + tx2 * 2 + sp * 64) = pac[sp];
    }
    __syncthreads();

    // ---- final: out[s] = sum of 16 partials + b2 --------------------------
    if (t < 128) {
        float sum = sh[OFF_B2];
#pragma unroll
        for (int g = 0; g < 16; g++)
            sum += sh[OFF_PART + g * XSTR + t];
        out[s0 + t] = sum;
    }
}

// ---------------------------------------------------------------------------
extern "C" void kernel_launch(void* const* d_in, const int* in_sizes, int n_in,
                              void* d_out, int out_size) {
    const float* pov   = (const float*)d_in[0];
    const float* white = (const float*)d_in[1];
    const float* black = (const float*)d_in[2];
    const float* Ww    = (const float*)d_in[3];
    const float* bw    = (const float*)d_in[4];
    const float* Wb    = (const float*)d_in[5];
    const float* bb    = (const float*)d_in[6];
    const float* W0    = (const float*)d_in[7];
    const float* b0    = (const float*)d_in[8];
    const float* W1    = (const float*)d_in[9];
    const float* b1    = (const float*)d_in[10];
    const float* W2    = (const float*)d_in[11];
    const float* b2    = (const float*)d_in[12];

    const int B = in_sizes[0];

    cudaFuncSetAttribute(nnue_kernel,
                         cudaFuncAttributeMaxDynamicSharedMemorySize, SMEM_BYTES);

    nnue_setup_kernel<<<25, 256>>>(Ww, Wb, W0, W1);
    nnue_kernel<<<B / 128, 256, SMEM_BYTES>>>(pov, white, black, bw, bb,
                                              b0, b1, W2, b2, (float*)d_out);
}

// round 6
// speedup vs baseline: 1.1765x; 1.1765x over previous
#include <cuda_runtime.h>
#include <cstdint>

// ===========================================================================
// NNUE eval via tensor-core mma.sync (tf32, m16n8k8) — baseline sm_80 PTX,
// valid on the compute_103 target (tcgen05 is rejected by this toolchain).
// 148 persistent CTAs x 256 threads; tile = 256 samples; warp owns 32 rows.
// ===========================================================================

__device__ __forceinline__ uint32_t f2tf32(float f) {
    uint32_t r; asm("cvt.rna.tf32.f32 %0, %1;" : "=r"(r) : "f"(f)); return r;
}

__device__ __forceinline__ void mma8(float* d,
                                     uint32_t a0, uint32_t a1, uint32_t a2, uint32_t a3,
                                     uint32_t b0, uint32_t b1) {
    asm volatile(
        "mma.sync.aligned.m16n8k8.row.col.f32.tf32.tf32.f32 "
        "{%0,%1,%2,%3}, {%4,%5,%6,%7}, {%8,%9}, {%0,%1,%2,%3};"
        : "+f"(d[0]), "+f"(d[1]), "+f"(d[2]), "+f"(d[3])
        : "r"(a0), "r"(a1), "r"(a2), "r"(a3), "r"(b0), "r"(b1));
}

// ---- pre-packed per-lane B fragments (device globals) ---------------------
// Bf[(step*NT + tn)*32 + lane][e] ; e=0:(k=q,n=g), e=1:(k=q+4,n=g)
__device__ uint32_t g_Bf1[13 * 8 * 32 * 2];
__device__ uint32_t g_Bf2[8 * 4 * 32 * 2];
__device__ uint32_t g_Bf3[4 * 4 * 32 * 2];

__global__ void nnue_setup(const float* __restrict__ Ww,
                           const float* __restrict__ Wb,
                           const float* __restrict__ W0,
                           const float* __restrict__ W1) {
    int t = blockIdx.x * blockDim.x + threadIdx.x;
    if (t < 6656) {   // 13*8*32*2
        int e = t & 1, lane = (t >> 1) & 31, tn = (t >> 6) & 7, s = t >> 9;
        int n = 8 * tn + (lane >> 2);
        int k = 8 * s + (lane & 3) + 4 * e;
        float v = 0.0f;
        if (k < 98) {
            if (n < 32) v = Ww[n * 98 + k];
            else { int kk = k + 49; if (kk >= 98) kk -= 98; v = Wb[(n - 32) * 98 + kk]; }
        }
        g_Bf1[t] = f2tf32(v);
    }
    if (t < 2048) {   // 8*4*32*2
        int e = t & 1, lane = (t >> 1) & 31, tn = (t >> 6) & 3, s = t >> 8;
        int n = 8 * tn + (lane >> 2);
        int k = 8 * s + (lane & 3) + 4 * e;
        g_Bf2[t] = f2tf32(W0[n * 64 + k]);
    }
    if (t < 1024) {   // 4*4*32*2
        int e = t & 1, lane = (t >> 1) & 31, tn = (t >> 6) & 3, s = t >> 8;
        int n = 8 * tn + (lane >> 2);
        int k = 8 * s + (lane & 3) + 4 * e;
        g_Bf3[t] = f2tf32(W1[n * 32 + k]);
    }
}

// ---- smem layout (u32 offsets) --------------------------------------------
// X pair layout, row stride 104: idx = row*104 + (step*4+q)*2 + e
//   holds (X[row][8s+q], X[row][8s+q+4]) as tf32.
// base overlays XP with stride 72; x0 uses stride 40. All strides ≡ 8 (mod 32)
// -> conflict-free LDS.64 A-fragment loads.
#define U_XP    0          // 256*104 = 26624  (base overlay: 256*72 <= 18432)
#define U_X0    26624      // 256*40  = 10240
#define U_BF1   36864      // 6656
#define U_BF2   43520      // 2048
#define U_BF3   45568      // 1024
#define U_BIAS1 46592      // 64
#define U_B0    46656      // 32
#define U_B1    46688      // 32
#define U_W2    46720      // 64
#define U_POV   46784      // 256
#define U_B2    47040      // 1
#define SMEM_BYTES (47044 * 4)

__global__ __launch_bounds__(256)
void nnue_mma(const float* __restrict__ pov,
              const float* __restrict__ white,
              const float* __restrict__ black,
              const float* __restrict__ bw,
              const float* __restrict__ bb,
              const float* __restrict__ b0,
              const float* __restrict__ b1,
              const float* __restrict__ W2,
              const float* __restrict__ b2,
              float* __restrict__ out, int ntiles) {
    extern __shared__ __align__(16) uint32_t shu[];
    float* shf = (float*)shu;
    const int t = threadIdx.x;
    const int lane = t & 31, wid = t >> 5;
    const int g = lane >> 2, q = lane & 3;
    const int r0 = wid * 32;

    // ---- one-time: fragments + vectors ------------------------------------
    {
        uint4* d = (uint4*)(shu + U_BF1); const uint4* s = (const uint4*)g_Bf1;
        for (int i = t; i < 1664; i += 256) d[i] = s[i];
        d = (uint4*)(shu + U_BF2); s = (const uint4*)g_Bf2;
        for (int i = t; i < 512; i += 256) d[i] = s[i];
        d = (uint4*)(shu + U_BF3); s = (const uint4*)g_Bf3;
        for (int i = t; i < 256; i += 256) d[i] = s[i];
    }
    if (t < 64) shf[U_BIAS1 + t] = (t < 32) ? bw[t] : bb[t - 32];
    if (t < 64) shf[U_W2 + t]    = W2[t];
    if (t < 32) shf[U_B0 + t]    = b0[t];
    if (t < 32) shf[U_B1 + t]    = b1[t];
    if (t == 0) shf[U_B2]        = b2[0];
    __syncthreads();
    const float b2val = shf[U_B2];

    for (int tile = blockIdx.x; tile < ntiles; tile += gridDim.x) {
        const size_t s0 = (size_t)tile * 256;

        // ---- stage X (tf32, pair layout) + pov ----------------------------
        for (int i = t; i < 256 * 49; i += 256) {
            int s = (unsigned)i / 49u;
            int k = i - s * 49;
            float wv = white[s0 * 49 + i];
            float bv = black[s0 * 49 + i];
            {   // col = k
                int st = k >> 3, r8 = k & 7;
                shu[U_XP + s * 104 + (st * 4 + (r8 & 3)) * 2 + (r8 >> 2)] = f2tf32(wv);
            }
            {   // col = k + 49
                int c = k + 49;
                int st = c >> 3, r8 = c & 7;
                shu[U_XP + s * 104 + (st * 4 + (r8 & 3)) * 2 + (r8 >> 2)] = f2tf32(bv);
            }
        }
        for (int i = t; i < 256 * 6; i += 256) {   // zero pad cols 98..103
            int s = i / 6, c = 98 + i % 6;
            int st = c >> 3, r8 = c & 7;
            shu[U_XP + s * 104 + (st * 4 + (r8 & 3)) * 2 + (r8 >> 2)] = 0;
        }
        shf[U_POV + t] = pov[s0 + t];
        __syncthreads();

        // ---- layer 1: D1[256x64] = X @ Wc^T, K=104 ------------------------
        float acc1[2][8][4];
#pragma unroll
        for (int m = 0; m < 2; m++)
#pragma unroll
            for (int tn = 0; tn < 8; tn++)
#pragma unroll
                for (int r = 0; r < 4; r++) acc1[m][tn][r] = 0.0f;

#pragma unroll
        for (int s = 0; s < 13; s++) {
            uint2 aa[2][2];
#pragma unroll
            for (int m = 0; m < 2; m++)
#pragma unroll
                for (int h = 0; h < 2; h++)
                    aa[m][h] = *(const uint2*)&shu[U_XP + (r0 + 16 * m + 8 * h + g) * 104
                                                   + (s * 4 + q) * 2];
#pragma unroll
            for (int tn = 0; tn < 8; tn++) {
                uint2 bv = *(const uint2*)&shu[U_BF1 + ((s * 8 + tn) * 32 + lane) * 2];
                mma8(acc1[0][tn], aa[0][0].x, aa[0][1].x, aa[0][0].y, aa[0][1].y, bv.x, bv.y);
                mma8(acc1[1][tn], aa[1][0].x, aa[1][1].x, aa[1][0].y, aa[1][1].y, bv.x, bv.y);
            }
        }
        __syncthreads();   // all warps done reading XP before base overlay

        // ---- epilogue 1: bias + pov mix + relu -> base (stride 72) --------
#pragma unroll
        for (int m = 0; m < 2; m++)
#pragma unroll
            for (int h = 0; h < 2; h++) {
                int row = r0 + 16 * m + 8 * h + g;
                float p  = shf[U_POV + row];
                float q1 = 1.0f - p;
#pragma unroll
                for (int tn = 0; tn < 4; tn++)
#pragma unroll
                    for (int c = 0; c < 2; c++) {
                        int col = 8 * tn + 2 * q + c;
                        float lo = acc1[m][tn][2 * h + c]     + shf[U_BIAS1 + col];
                        float hi = acc1[m][tn + 4][2 * h + c] + shf[U_BIAS1 + 32 + col];
                        float v0 = fmaxf(p * lo + q1 * hi, 0.0f);
                        float v1 = fmaxf(p * hi + q1 * lo, 0.0f);
                        int st0 = col >> 3, r8 = col & 7;
                        shu[U_XP + row * 72 + (st0 * 4 + (r8 & 3)) * 2 + (r8 >> 2)] = f2tf32(v0);
                        int colB = col + 32;
                        int stB = colB >> 3, rB = colB & 7;
                        shu[U_XP + row * 72 + (stB * 4 + (rB & 3)) * 2 + (rB >> 2)] = f2tf32(v1);
                    }
            }
        __syncwarp();

        // ---- layer 2: D2[256x32] = base @ W0^T, K=64 ----------------------
        float acc2[2][4][4];
#pragma unroll
        for (int m = 0; m < 2; m++)
#pragma unroll
            for (int tn = 0; tn < 4; tn++)
#pragma unroll
                for (int r = 0; r < 4; r++) acc2[m][tn][r] = 0.0f;

#pragma unroll
        for (int s = 0; s < 8; s++) {
            uint2 aa[2][2];
#pragma unroll
            for (int m = 0; m < 2; m++)
#pragma unroll
                for (int h = 0; h < 2; h++)
                    aa[m][h] = *(const uint2*)&shu[U_XP + (r0 + 16 * m + 8 * h + g) * 72
                                                   + (s * 4 + q) * 2];
#pragma unroll
            for (int tn = 0; tn < 4; tn++) {
                uint2 bv = *(const uint2*)&shu[U_BF2 + ((s * 4 + tn) * 32 + lane) * 2];
                mma8(acc2[0][tn], aa[0][0].x, aa[0][1].x, aa[0][0].y, aa[0][1].y, bv.x, bv.y);
                mma8(acc2[1][tn], aa[1][0].x, aa[1][1].x, aa[1][0].y, aa[1][1].y, bv.x, bv.y);
            }
        }

        // ---- epilogue 2: x0 = relu(D2+b0) -> X0 (stride 40); W2[0:32] dot -
        float dot[2][2] = {{0.0f, 0.0f}, {0.0f, 0.0f}};
#pragma unroll
        for (int m = 0; m < 2; m++)
#pragma unroll
            for (int h = 0; h < 2; h++) {
                int row = r0 + 16 * m + 8 * h + g;
#pragma unroll
                for (int tn = 0; tn < 4; tn++)
#pragma unroll
                    for (int c = 0; c < 2; c++) {
                        int col = 8 * tn + 2 * q + c;
                        float v = fmaxf(acc2[m][tn][2 * h + c] + shf[U_B0 + col], 0.0f);
                        dot[m][h] += v * shf[U_W2 + col];
                        int r8 = col & 7;
                        shu[U_X0 + row * 40 + (tn * 4 + (r8 & 3)) * 2 + (r8 >> 2)] = f2tf32(v);
                    }
            }
        __syncwarp();

        // ---- layer 3: D3[256x32] = x0 @ W1^T, K=32 ------------------------
        float acc3[2][4][4];
#pragma unroll
        for (int m = 0; m < 2; m++)
#pragma unroll
            for (int tn = 0; tn < 4; tn++)
#pragma unroll
                for (int r = 0; r < 4; r++) acc3[m][tn][r] = 0.0f;

#pragma unroll
        for (int s = 0; s < 4; s++) {
            uint2 aa[2][2];
#pragma unroll
            for (int m = 0; m < 2; m++)
#pragma unroll
                for (int h = 0; h < 2; h++)
                    aa[m][h] = *(const uint2*)&shu[U_X0 + (r0 + 16 * m + 8 * h + g) * 40
                                                   + (s * 4 + q) * 2];
#pragma unroll
            for (int tn = 0; tn < 4; tn++) {
                uint2 bv = *(const uint2*)&shu[U_BF3 + ((s * 4 + tn) * 32 + lane) * 2];
                mma8(acc3[0][tn], aa[0][0].x, aa[0][1].x, aa[0][0].y, aa[0][1].y, bv.x, bv.y);
                mma8(acc3[1][tn], aa[1][0].x, aa[1][1].x, aa[1][0].y, aa[1][1].y, bv.x, bv.y);
            }
        }

        // ---- epilogue 3: dot += relu(D3+b1).W2[32:]; reduce; store --------
#pragma unroll
        for (int m = 0; m < 2; m++)
#pragma unroll
            for (int h = 0; h < 2; h++) {
#pragma unroll
                for (int tn = 0; tn < 4; tn++)
#pragma unroll
                    for (int c = 0; c < 2; c++) {
                        int col = 8 * tn + 2 * q + c;
                        float v = fmaxf(acc3[m][tn][2 * h + c] + shf[U_B1 + col], 0.0f);
                        dot[m][h] += v * shf[U_W2 + 32 + col];
                    }
                float d = dot[m][h];
                d += __shfl_xor_sync(0xffffffffu, d, 1);
                d += __shfl_xor_sync(0xffffffffu, d, 2);
                if (q == 0)
                    out[s0 + r0 + 16 * m + 8 * h + g] = d + b2val;
            }
        __syncthreads();   // XP/base region free before next staging
    }
}

// ---------------------------------------------------------------------------
extern "C" void kernel_launch(void* const* d_in, const int* in_sizes, int n_in,
                              void* d_out, int out_size) {
    const float* pov   = (const float*)d_in[0];
    const float* white = (const float*)d_in[1];
    const float* black = (const float*)d_in[2];
    const float* Ww    = (const float*)d_in[3];
    const float* bw    = (const float*)d_in[4];
    const float* Wb    = (const float*)d_in[5];
    const float* bb    = (const float*)d_in[6];
    const float* W0    = (const float*)d_in[7];
    const float* b0    = (const float*)d_in[8];
    const float* W1    = (const float*)d_in[9];
    const float* b1    = (const float*)d_in[10];
    const float* W2    = (const float*)d_in[11];
    const float* b2    = (const float*)d_in[12];

    const int B = in_sizes[0];
    const int ntiles = B / 256;

    cudaFuncSetAttribute(nnue_mma,
                         cudaFuncAttributeMaxDynamicSharedMemorySize, SMEM_BYTES);

    nnue_setup<<<26, 256>>>(Ww, Wb, W0, W1);
    nnue_mma<<<148, 256, SMEM_BYTES>>>(pov, white, black, bw, bb,
                                       b0, b1, W2, b2, (float*)d_out, ntiles);
}